// round 12
// baseline (speedup 1.0000x reference)
#include <cuda_runtime.h>
#include <cstdint>
#include <math.h>

typedef uint32_t u32;
typedef unsigned long long u64;

__device__ __forceinline__ u64 pack2(float lo, float hi){
    u64 d; asm("mov.b64 %0, {%1, %2};" : "=l"(d) : "f"(lo), "f"(hi)); return d;
}
__device__ __forceinline__ u64 fma2(u64 a, u64 b, u64 c){
    u64 d; asm("fma.rn.f32x2 %0, %1, %2, %3;" : "=l"(d) : "l"(a), "l"(b), "l"(c)); return d;
}
__device__ __forceinline__ u64 add2(u64 a, u64 b){
    u64 d; asm("add.rn.f32x2 %0, %1, %2;" : "=l"(d) : "l"(a), "l"(b)); return d;
}
__device__ __forceinline__ float lo2(u64 v){ return __int_as_float((unsigned)(v & 0xffffffffull)); }
__device__ __forceinline__ float hi2(u64 v){ return __int_as_float((unsigned)(v >> 32)); }
__device__ __forceinline__ float tanha(float v){
    float r; asm("tanh.approx.f32 %0, %1;" : "=f"(r) : "f"(v)); return r;
}

// ---------------- scratch ----------------
// packed per-(row,pair) trig-poly coefficients, patch-ready layout:
// g_Cpk[(r*7+j)*90 + i01*10 + t3*3 + t2] = pack2(C[p=2j], C[p=2j+1]); i01 = t0*3+t1
__device__ u64 g_Cpk[98 * 90];
// transposed partials: g_part[(r*3+q)*16384 + img], q in {Q, S, S2}
__device__ float g_part[42 * 16384];

// ---------------- kernel 0: fused build (G row per thread + C dot) ----------------
// G[L][k] = (1/16) sum_{ch in 2^4} sg(ch) * (ur[k][m(ch)]ur[k][n(ch)] + ui*ui)
// digits of L = t3*27 + t0*9 + t1*3 + t2 select per-qubit basis {1, cos, sin}.
__global__ __launch_bounds__(96)
void build_kernel(const float* __restrict__ U_re,
                  const float* __restrict__ U_im,
                  const float* __restrict__ w_cls)
{
    __shared__ float sur[256], sui[256];
    const int blk = blockIdx.x;       // r*7 + j
    const int L   = threadIdx.x;      // 0..95 (81 active)

    for (int i = threadIdx.x; i < 256; i += 96) { sur[i] = U_re[i]; sui[i] = U_im[i]; }
    __syncthreads();
    if (L >= 81) return;

    const int t3 = L / 27, rem = L - 27 * t3;
    const int t0 = rem / 9, r9 = rem - 9 * t0;
    const int t1 = r9 / 3,  t2 = r9 - 3 * t1;
    const int tq[4] = { t0, t1, t2, t3 };

    // precompute (m, n, sign) for the 16 bit-choices once
    int mA[16], nA[16];
    float sgA[16];
    #pragma unroll 1
    for (int ch = 0; ch < 16; ch++) {
        int m = 0, n = 0; float sg = 1.f;
        #pragma unroll
        for (int q = 0; q < 4; q++) {
            int o = (ch >> q) & 1;
            int tv = tq[q];
            int bm, bn;
            if (tv == 2) { bm = o; bn = 1 - o; }
            else         { bm = o; bn = o; if (tv == 1 && o) sg = -sg; }
            m |= bm << (3 - q);
            n |= bn << (3 - q);
        }
        mA[ch] = m; nA[ch] = n; sgA[ch] = sg;
    }

    // C[pA], C[pB] accumulated directly: dot of G row with v_k weights
    const int p0 = 2 * blk;
    const float* wa = w_cls + 1 + 4 * p0;
    const float* wb = wa + 4;
    const float a0 = wa[0], a1 = wa[1], a2 = wa[2], a3 = wa[3];
    const float b0 = wb[0], b1 = wb[1], b2 = wb[2], b3 = wb[3];

    float accA = 0.f, accB = 0.f;
    #pragma unroll 1
    for (int k = 0; k < 16; k++) {
        const float* urk = sur + k * 16;
        const float* uik = sui + k * 16;
        float g = 0.f;
        #pragma unroll
        for (int ch = 0; ch < 16; ch++)
            g = fmaf(sgA[ch], fmaf(urk[mA[ch]], urk[nA[ch]], uik[mA[ch]] * uik[nA[ch]]), g);
        g *= (1.f / 16.f);
        float vA = ((k & 8) ? -a0 : a0) + ((k & 4) ? -a1 : a1)
                 + ((k & 2) ? -a2 : a2) + ((k & 1) ? -a3 : a3);
        float vB = ((k & 8) ? -b0 : b0) + ((k & 4) ? -b1 : b1)
                 + ((k & 2) ? -b2 : b2) + ((k & 1) ? -b3 : b3);
        accA = fmaf(vA, g, accA);
        accB = fmaf(vB, g, accB);
    }
    const int i01 = t0 * 3 + t1;
    g_Cpk[blk * 90 + i01 * 10 + t3 * 3 + t2] = pack2(accA, accB);
}

// ---------------- kernel 1: per-patch trig-poly eval (unchanged core) ----------------
#define PK_THREADS 128

__global__ __launch_bounds__(PK_THREADS)
void patch_kernel(const float* __restrict__ x, int bsz)
{
    __shared__ __align__(16) u64 sC[7 * 90];        // 5040 B
    __shared__ float spx[PK_THREADS * 58];          // 29696 B

    const int r    = blockIdx.x;                    // 0..13
    const int tid  = threadIdx.x;
    const int img0 = blockIdx.y * PK_THREADS;
    const int img  = img0 + tid;
    const int nimg = min(PK_THREADS, bsz - img0);

    for (int i = tid; i < 7 * 90; i += PK_THREADS)
        sC[i] = g_Cpk[r * 630 + i];

    const float* xbase = x + (size_t)img0 * 784 + r * 56;
    for (int idx = tid; idx < PK_THREADS * 56; idx += PK_THREADS) {
        int i = idx / 56, f = idx - i * 56;
        spx[i * 58 + f] = (i < nimg) ? xbase[(size_t)i * 784 + f] : 0.f;
    }
    __syncthreads();

    const float* my = spx + tid * 58;
    const u64 ONEv = pack2(1.f, 1.f);

    u64 sQ = 0ull;
    float sp = 0.f, sqs = 0.f;

    #pragma unroll 1
    for (int j = 0; j < 7; j++) {
        float2 a01 = *reinterpret_cast<const float2*>(my + 4 * j);
        float2 b01 = *reinterpret_cast<const float2*>(my + 4 * j + 2);
        float2 a23 = *reinterpret_cast<const float2*>(my + 28 + 4 * j);
        float2 b23 = *reinterpret_cast<const float2*>(my + 30 + 4 * j);

        sp  += (a01.x + a01.y + b01.x + b01.y) + (a23.x + a23.y + b23.x + b23.y);
        sqs += fmaf(a01.x,a01.x, fmaf(a01.y,a01.y, fmaf(b01.x,b01.x, b01.y*b01.y)))
             + fmaf(a23.x,a23.x, fmaf(a23.y,a23.y, fmaf(b23.x,b23.x, b23.y*b23.y)));

        float ca0,sa0,ca1,sa1,ca2,sa2,ca3,sa3;
        float cb0,sb0,cb1,sb1,cb2,sb2,cb3,sb3;
        __sincosf(a01.x, &sa0, &ca0);  __sincosf(a01.y, &sa1, &ca1);
        __sincosf(a23.x, &sa2, &ca2);  __sincosf(a23.y, &sa3, &ca3);
        __sincosf(b01.x, &sb0, &cb0);  __sincosf(b01.y, &sb1, &cb1);
        __sincosf(b23.x, &sb2, &cb2);  __sincosf(b23.y, &sb3, &cb3);

        u64 Fc0 = pack2(ca0, cb0), Fs0 = pack2(sa0, sb0);
        u64 Fc1 = pack2(ca1, cb1), Fs1 = pack2(sa1, sb1);
        u64 Fc2 = pack2(ca2, cb2), Fs2 = pack2(sa2, sb2);
        u64 Fc3 = pack2(ca3, cb3), Fs3 = pack2(sa3, sb3);

        const u64* Cj = sC + j * 90;
        u64 h0 = 0ull, h1 = 0ull, h2 = 0ull;

        #pragma unroll
        for (int i01 = 0; i01 < 9; i01++) {
            const u64* base = Cj + i01 * 10;
            ulonglong2 q01 = *reinterpret_cast<const ulonglong2*>(base + 0);
            ulonglong2 q23 = *reinterpret_cast<const ulonglong2*>(base + 2);
            ulonglong2 q45 = *reinterpret_cast<const ulonglong2*>(base + 4);
            ulonglong2 q67 = *reinterpret_cast<const ulonglong2*>(base + 6);
            u64 q8 = base[8];
            u64 av0 = fma2(q67.x, Fs3, fma2(q23.y, Fc3, q01.x));
            u64 av1 = fma2(q67.y, Fs3, fma2(q45.x, Fc3, q01.y));
            u64 av2 = fma2(q8,    Fs3, fma2(q45.y, Fc3, q23.x));
            u64 g   = fma2(av2, Fs2, fma2(av1, Fc2, av0));
            const int t1v = i01 % 3;
            u64 w = (t1v == 0) ? ONEv : ((t1v == 1) ? Fc1 : Fs1);
            if (i01 < 3)      h0 = fma2(g, w, h0);
            else if (i01 < 6) h1 = fma2(g, w, h1);
            else              h2 = fma2(g, w, h2);
        }
        sQ = add2(sQ, fma2(h2, Fs0, fma2(h1, Fc0, h0)));
    }

    if (img < bsz) {
        g_part[(r * 3 + 0) * 16384 + img] = lo2(sQ) + hi2(sQ);
        g_part[(r * 3 + 1) * 16384 + img] = sp;
        g_part[(r * 3 + 2) * 16384 + img] = sqs;
    }
}

// ---------------- kernel 2: 4-thread-per-image reduce + head + sigmoid ----------------
__global__ void head_kernel(
    const float* __restrict__ w_in,  const float* __restrict__ b_in,
    const float* __restrict__ scale_in, const float* __restrict__ shift_in,
    const float* __restrict__ Wc,    const float* __restrict__ bc,
    const float* __restrict__ scalec, const float* __restrict__ shiftc,
    const float* __restrict__ w_out, const float* __restrict__ b_out,
    const float* __restrict__ w_cls, const float* __restrict__ b_cls,
    float* __restrict__ out, int Lc, int bsz)
{
    const int t   = blockIdx.x * blockDim.x + threadIdx.x;
    const int img = t >> 2;
    const int s   = t & 3;
    const bool v  = img < bsz;

    float Q = 0.f, S = 0.f, S2 = 0.f;
    if (v) {
        #pragma unroll
        for (int u = 0; u < 4; u++) {
            int r = s + 4 * u;
            if (r < 14) {
                Q  += g_part[(r * 3 + 0) * 16384 + img];
                S  += g_part[(r * 3 + 1) * 16384 + img];
                S2 += g_part[(r * 3 + 2) * 16384 + img];
            }
        }
    }
    const unsigned m = 0xffffffffu;
    Q  += __shfl_down_sync(m, Q,  2, 4);  Q  += __shfl_down_sync(m, Q,  1, 4);
    S  += __shfl_down_sync(m, S,  2, 4);  S  += __shfl_down_sync(m, S,  1, 4);
    S2 += __shfl_down_sync(m, S2, 2, 4);  S2 += __shfl_down_sync(m, S2, 1, 4);

    if (v && s == 0) {
        float mean = S * (1.f/784.f);
        float var  = (S2 - S*S*(1.f/784.f)) * (1.f/783.f);
        float stdv = sqrtf(fmaxf(var, 0.f));
        float h0 = mean, h1 = stdv;
        float t0 = tanha(fmaf(w_in[0],h0, fmaf(w_in[1],h1, b_in[0]))) * scale_in[0] + shift_in[0];
        float t1 = tanha(fmaf(w_in[2],h0, fmaf(w_in[3],h1, b_in[1]))) * scale_in[1] + shift_in[1];
        h0 = t0; h1 = t1;
        for (int l = 0; l < Lc; l++) {
            float u0 = tanha(fmaf(Wc[l*4+0],h0, fmaf(Wc[l*4+1],h1, bc[l*2+0]))) * scalec[l*2+0] + shiftc[l*2+0];
            float u1 = tanha(fmaf(Wc[l*4+2],h0, fmaf(Wc[l*4+3],h1, bc[l*2+1]))) * scalec[l*2+1] + shiftc[l*2+1];
            h0 = u0; h1 = u1;
        }
        float cls   = fmaf(w_out[0],h0, fmaf(w_out[1],h1, b_out[0]));
        float logit = fmaf(w_cls[0], cls, b_cls[0]) + Q;
        out[img] = 1.f / (1.f + __expf(-logit));
    }
}

// ---------------- launch ----------------
extern "C" void kernel_launch(void* const* d_in, const int* in_sizes, int n_in,
                              void* d_out, int out_size)
{
    const float* x        = (const float*)d_in[0];
    const float* w_in     = (const float*)d_in[1];
    const float* b_in     = (const float*)d_in[2];
    const float* scale_in = (const float*)d_in[3];
    const float* shift_in = (const float*)d_in[4];
    const float* Wc       = (const float*)d_in[5];
    const float* bc       = (const float*)d_in[6];
    const float* scalec   = (const float*)d_in[7];
    const float* shiftc   = (const float*)d_in[8];
    const float* w_out    = (const float*)d_in[9];
    const float* b_out    = (const float*)d_in[10];
    const float* U_re     = (const float*)d_in[11];
    const float* U_im     = (const float*)d_in[12];
    const float* w_cls    = (const float*)d_in[13];
    const float* b_cls    = (const float*)d_in[14];
    float* out = (float*)d_out;

    const int bsz = in_sizes[0] / 784;
    const int Lc  = in_sizes[5] / 4;

    build_kernel<<<98, 96>>>(U_re, U_im, w_cls);

    dim3 grid1(14, (bsz + PK_THREADS - 1) / PK_THREADS);
    patch_kernel<<<grid1, PK_THREADS>>>(x, bsz);

    head_kernel<<<(bsz * 4 + 127) / 128, 128>>>(w_in, b_in, scale_in, shift_in,
                                                Wc, bc, scalec, shiftc,
                                                w_out, b_out, w_cls, b_cls,
                                                out, Lc, bsz);
}